// round 15
// baseline (speedup 1.0000x reference)
#include <cuda_runtime.h>
#include <cuda_fp16.h>
#include <cstdint>

#define NBLOCKS  888          // 148 SMs * 6 resident blocks -> single wave
#define NTHREADS 256
#define NWARPS   (NBLOCKS * NTHREADS / 32)
#define CAP_NODES 500000

// Device globals (no allocation allowed). Zero-initialized at load.
__device__ unsigned char g_q[(size_t)CAP_NODES * 64];  // 32 MB int8 unit vectors
__device__ float         g_part[NBLOCKS];
__device__ unsigned int  g_bar;     // phase barrier; last block resets to 0
__device__ unsigned int  g_count;   // completion counter; last block resets to 0

__device__ __forceinline__ float dot4f(float4 a, float4 b) {
    return a.x * b.x + a.y * b.y + a.z * b.z + a.w * b.w;
}

__device__ __forceinline__ unsigned int pack4_s8(float a, float b, float c, float d) {
    const int ia = __float2int_rn(a), ib = __float2int_rn(b);
    const int ic = __float2int_rn(c), id = __float2int_rn(d);
    return (unsigned int)(ia & 0xFF) | ((unsigned int)(ib & 0xFF) << 8) |
           ((unsigned int)(ic & 0xFF) << 16) | ((unsigned int)(id & 0xFF) << 24);
}

// Fused: phase 1 normalizes into g_q, grid barrier, phase 2 computes loss.
__global__ void __launch_bounds__(NTHREADS, 6)
fused_kernel(const float* __restrict__ feats,
             const void* __restrict__ tplts_raw,
             int n_trip, int n_nodes, float* __restrict__ out)
{
    const int lane = threadIdx.x & 31;
    const int w    = (int)((blockIdx.x * blockDim.x + threadIdx.x) >> 5);
    const int warp_in_blk = threadIdx.x >> 5;

    // ---------------- Phase 1: normalize + int8 quantize ----------------
    {
        const int g  = lane >> 3;     // row-group 0..3 within warp
        const int li = lane & 7;      // lane within group
        const int n_quads = (n_nodes + 3) >> 2;

        for (int q = w; q < n_quads; q += NWARPS) {
            const int r = q * 4 + g;
            const bool valid = (r < n_nodes);
            const int rs = valid ? r : 0;

            // Evict-first: don't let the fp32 stream evict the int8 table.
            const float4* row = (const float4*)feats + ((long long)rs * 16 + li);
            const float4 v0 = __ldcs(row);
            const float4 v1 = __ldcs(row + 8);

            float nn = dot4f(v0, v0) + dot4f(v1, v1);
            #pragma unroll
            for (int off = 4; off > 0; off >>= 1)
                nn += __shfl_xor_sync(0xFFFFFFFFu, nn, off);

            // norm clamp at 1e-8 (reference eps) == norm^2 clamp at 1e-16
            const float inv = rsqrtf(fmaxf(nn, 1e-16f)) * 127.0f;

            uint2 pack;
            pack.x = pack4_s8(v0.x * inv, v0.y * inv, v0.z * inv, v0.w * inv);
            pack.y = pack4_s8(v1.x * inv, v1.y * inv, v1.z * inv, v1.w * inv);

            if (valid) {
                ((uint2*)(g_q + (size_t)rs * 64))[li] = pack;
            }
        }
    }

    // ---------------- Grid barrier (all 888 blocks co-resident) ----------
    __threadfence();
    __syncthreads();
    if (threadIdx.x == 0) {
        atomicAdd(&g_bar, 1u);
        volatile unsigned int* vb = &g_bar;
        while (*vb < (unsigned int)NBLOCKS) { __nanosleep(64); }
    }
    __syncthreads();
    __threadfence();

    // ---------------- Phase 2: triplet loss over int8 unit vectors -------
    const int grp = lane >> 2;        // triplet-group 0..7 within warp
    const int li4 = lane & 3;         // lane within group

    // Self-detect index dtype: int64 values < 2^31 -> odd 32-bit words all 0.
    const unsigned int* raw = (const unsigned int*)tplts_raw;
    const unsigned int probe = raw[2 * lane + 1];
    const int is64 = (__ballot_sync(0xFFFFFFFFu, probe != 0u) == 0u) ? 1 : 0;

    const int stride = is64 ? 2 : 1;
    const int* c0 = (const int*)tplts_raw;
    const int* c1 = c0 + n_trip * stride;
    const int* c2 = c1 + n_trip * stride;

    const int n_oct = (n_trip + 7) >> 3;   // 8 triplets per octet
    const unsigned int idx_max =
        (unsigned int)((n_nodes < CAP_NODES ? n_nodes : CAP_NODES) - 1);

    // Static contiguous span for this warp.
    const int per = (n_oct + NWARPS - 1) / NWARPS;
    const int o_beg = w * per;
    const int o_end = min(o_beg + per, n_oct);

    float local = 0.0f;
    const float inv127sq = 1.0f / 16129.0f;   // 1/(127*127)

    #define LOAD_IDX(ov, IA_, IP_, IN_, T_)                                  \
        {                                                                    \
            (T_) = (ov) * 8 + grp;                                           \
            const int ts_ = min((T_), n_trip - 1) * stride;                  \
            (IA_) = min((unsigned int)c0[ts_], idx_max);                     \
            (IP_) = min((unsigned int)c1[ts_], idx_max);                     \
            (IN_) = min((unsigned int)c2[ts_], idx_max);                     \
        }

    #define GATHER(IA_, IP_, IN_, A_, P_, N_)                                \
        {                                                                    \
            (A_) = __ldg((const uint4*)(g_q + (size_t)(IA_) * 64) + li4);    \
            (P_) = __ldg((const uint4*)(g_q + (size_t)(IP_) * 64) + li4);    \
            (N_) = __ldg((const uint4*)(g_q + (size_t)(IN_) * 64) + li4);    \
        }

    if (o_beg < o_end) {
        int o = o_beg;
        unsigned int ia, ip, in;
        int t;
        LOAD_IDX(o, ia, ip, in, t);
        uint4 A, P, N;
        GATHER(ia, ip, in, A, P, N);

        for (;;) {
            const int on = o + 1;
            const bool have_next = (on < o_end);

            // Prefetch next octet to overlap with compute below.
            uint4 A2, P2, N2;
            int t2 = 0;
            if (have_next) {
                unsigned int ia2, ip2, in2;
                LOAD_IDX(on, ia2, ip2, in2, t2);
                GATHER(ia2, ip2, in2, A2, P2, N2);
            }

            // Compute current octet.
            const int* aw = (const int*)&A;
            const int* pw = (const int*)&P;
            const int* nw = (const int*)&N;
            int dap = 0, dan = 0;
            #pragma unroll
            for (int j = 0; j < 4; j++) {
                dap = __dp4a(aw[j], pw[j], dap);
                dan = __dp4a(aw[j], nw[j], dan);
            }
            dap += __shfl_xor_sync(0xFFFFFFFFu, dap, 2);
            dap += __shfl_xor_sync(0xFFFFFFFFu, dap, 1);
            dan += __shfl_xor_sync(0xFFFFFFFFu, dan, 2);
            dan += __shfl_xor_sync(0xFFFFFFFFu, dan, 1);

            if (li4 == 0) {
                const float cs_ap = (float)dap * inv127sq;
                const float cs_an = (float)dan * inv127sq;
                // u = 5 - 10*cs_ap, v = 10*cs_an - 5 ; both in [-15, 15]:
                // softplus(u)+softplus(v) = log((1+e^u)(1+e^v)), safe in fp32
                const float u = fmaf(-10.0f, cs_ap, 5.0f);
                const float v = fmaf( 10.0f, cs_an, -5.0f);
                const float add = __logf((1.0f + __expf(u)) * (1.0f + __expf(v)));
                local += (t < n_trip) ? add : 0.0f;
            }

            if (!have_next) break;
            A = A2; P = P2; N = N2; t = t2; o = on;
        }
    }
    #undef LOAD_IDX
    #undef GATHER

    // Block reduction
    #pragma unroll
    for (int off = 16; off > 0; off >>= 1)
        local += __shfl_xor_sync(0xFFFFFFFFu, local, off);

    __shared__ float s_part[NTHREADS / 32];
    __shared__ bool  s_last;
    if (lane == 0) s_part[warp_in_blk] = local;
    __syncthreads();
    if (threadIdx.x == 0) {
        float blk = 0.0f;
        #pragma unroll
        for (int i = 0; i < NTHREADS / 32; i++) blk += s_part[i];
        g_part[blockIdx.x] = blk;
        __threadfence();
        const unsigned int prev = atomicAdd(&g_count, 1u);
        s_last = (prev == NBLOCKS - 1);
    }
    __syncthreads();

    // Last finished block: final reduction, output, reset globals for replay.
    if (s_last) {
        double acc = 0.0;
        for (int i = threadIdx.x; i < NBLOCKS; i += NTHREADS)
            acc += (double)g_part[i];
        #pragma unroll
        for (int off = 16; off > 0; off >>= 1)
            acc += __shfl_xor_sync(0xFFFFFFFFu, acc, off);
        __shared__ double s_d[NTHREADS / 32];
        if (lane == 0) s_d[warp_in_blk] = acc;
        __syncthreads();
        if (threadIdx.x == 0) {
            double tot = 0.0;
            #pragma unroll
            for (int i = 0; i < NTHREADS / 32; i++) tot += s_d[i];
            out[0] = (float)(tot / (double)n_trip);
            g_count = 0;   // restore initial state for next graph replay
            g_bar   = 0;
        }
    }
}

extern "C" void kernel_launch(void* const* d_in, const int* in_sizes, int n_in,
                              void* d_out, int out_size)
{
    // Identify inputs by size: feats (32M elems) vs tplts (3M elems).
    int fi = 0, ti = 1;
    if (n_in >= 2 && in_sizes[1] > in_sizes[0]) { fi = 1; ti = 0; }

    const float* feats     = (const float*)d_in[fi];
    const void*  tplts_raw = d_in[ti];
    const int    n_trip    = in_sizes[ti] / 3;
    const int    n_nodes   = in_sizes[fi] / 64;
    float* out = (float*)d_out;

    fused_kernel<<<NBLOCKS, NTHREADS>>>(feats, tplts_raw, n_trip, n_nodes, out);
}

// round 16
// speedup vs baseline: 1.0410x; 1.0410x over previous
#include <cuda_runtime.h>
#include <cuda_fp16.h>
#include <cstdint>

#define NBLOCKS  888          // 148 SMs * 6 resident blocks -> single wave
#define NTHREADS 256
#define NWARPS   (NBLOCKS * NTHREADS / 32)
#define CAP_NODES 500000

// Device globals (no allocation allowed). Zero-initialized at load.
__device__ unsigned char g_q[(size_t)CAP_NODES * 64];  // 32 MB int8 unit vectors
__device__ float         g_part[NBLOCKS];
__device__ unsigned int  g_count;   // starts 0; last block resets to 0

__device__ __forceinline__ float dot4f(float4 a, float4 b) {
    return a.x * b.x + a.y * b.y + a.z * b.z + a.w * b.w;
}

__device__ __forceinline__ unsigned int pack4_s8(float a, float b, float c, float d) {
    const int ia = __float2int_rn(a), ib = __float2int_rn(b);
    const int ic = __float2int_rn(c), id = __float2int_rn(d);
    return (unsigned int)(ia & 0xFF) | ((unsigned int)(ib & 0xFF) << 8) |
           ((unsigned int)(ic & 0xFF) << 16) | ((unsigned int)(id & 0xFF) << 24);
}

// ---------- Pass 1: normalize rows, store int8 unit vectors (scale 127) ----
__global__ void __launch_bounds__(NTHREADS, 6)
normalize_kernel(const float* __restrict__ feats, int n_nodes)
{
    const int lane = threadIdx.x & 31;
    const int g    = lane >> 3;       // row-group 0..3 within warp
    const int li   = lane & 7;        // lane within group
    const int warp_g = (int)((blockIdx.x * blockDim.x + threadIdx.x) >> 5);

    const int n_quads = (n_nodes + 3) >> 2;

    for (int q = warp_g; q < n_quads; q += NWARPS) {
        const int r = q * 4 + g;
        const bool valid = (r < n_nodes);
        const int rs = valid ? r : 0;

        // Evict-first loads: don't let the fp32 stream evict the int8 table.
        const float4* row = (const float4*)feats + ((long long)rs * 16 + li);
        const float4 v0 = __ldcs(row);
        const float4 v1 = __ldcs(row + 8);

        float nn = dot4f(v0, v0) + dot4f(v1, v1);
        #pragma unroll
        for (int off = 4; off > 0; off >>= 1)
            nn += __shfl_xor_sync(0xFFFFFFFFu, nn, off);

        // norm clamp at 1e-8 (reference eps) == norm^2 clamp at 1e-16
        const float inv = rsqrtf(fmaxf(nn, 1e-16f)) * 127.0f;

        uint2 pack;
        pack.x = pack4_s8(v0.x * inv, v0.y * inv, v0.z * inv, v0.w * inv);
        pack.y = pack4_s8(v1.x * inv, v1.y * inv, v1.z * inv, v1.w * inv);

        if (valid) {
            // 8 lanes x 8B = 64B row, coalesced
            ((uint2*)(g_q + (size_t)rs * 64))[li] = pack;
        }
    }
}

// ---------- Pass 2: triplet loss over int8 unit vectors --------------------
// 4 lanes per vector, 8 triplets per warp-iteration, static contiguous spans,
// depth-2 prefetch. Warps whose whole span is valid run an unchecked loop.
__global__ void __launch_bounds__(NTHREADS, 6)
loss_kernel(const void* __restrict__ tplts_raw,
            int n_trip, int n_nodes, float* __restrict__ out)
{
    const int lane = threadIdx.x & 31;
    const int grp  = lane >> 2;       // triplet-group 0..7 within warp
    const int li   = lane & 3;        // lane within group
    const int w    = (int)((blockIdx.x * blockDim.x + threadIdx.x) >> 5);

    // Self-detect index dtype: int64 values < 2^31 -> odd 32-bit words all 0.
    const unsigned int* raw = (const unsigned int*)tplts_raw;
    const unsigned int probe = raw[2 * lane + 1];
    const int is64 = (__ballot_sync(0xFFFFFFFFu, probe != 0u) == 0u) ? 1 : 0;

    // Column base pointers in 32-bit words, with per-element stride.
    const int stride = is64 ? 2 : 1;
    const int* c0 = (const int*)tplts_raw;
    const int* c1 = c0 + n_trip * stride;
    const int* c2 = c1 + n_trip * stride;

    const int n_oct = (n_trip + 7) >> 3;   // 8 triplets per octet
    const unsigned int idx_max =
        (unsigned int)((n_nodes < CAP_NODES ? n_nodes : CAP_NODES) - 1);

    // Static contiguous span for this warp.
    const int per = (n_oct + NWARPS - 1) / NWARPS;
    const int o_beg = w * per;
    const int o_end = min(o_beg + per, n_oct);
    // All triplets in this warp's span valid? (n_oct <= 125000, no overflow)
    const bool all_valid = (o_end * 8) <= n_trip;

    float local = 0.0f;
    const float inv127sq = 1.0f / 16129.0f;   // 1/(127*127)

    // Index loads are streamed once: evict-first so they don't evict g_q.
    #define LOAD_IDX_U(ov, IA_, IP_, IN_)                                    \
        {                                                                    \
            const int ts_ = ((ov) * 8 + grp) * stride;                       \
            (IA_) = min((unsigned int)__ldcs(c0 + ts_), idx_max);            \
            (IP_) = min((unsigned int)__ldcs(c1 + ts_), idx_max);            \
            (IN_) = min((unsigned int)__ldcs(c2 + ts_), idx_max);            \
        }

    #define LOAD_IDX_C(ov, IA_, IP_, IN_, T_)                                \
        {                                                                    \
            (T_) = (ov) * 8 + grp;                                           \
            const int ts_ = min((T_), n_trip - 1) * stride;                  \
            (IA_) = min((unsigned int)__ldcs(c0 + ts_), idx_max);            \
            (IP_) = min((unsigned int)__ldcs(c1 + ts_), idx_max);            \
            (IN_) = min((unsigned int)__ldcs(c2 + ts_), idx_max);            \
        }

    #define GATHER(IA_, IP_, IN_, A_, P_, N_)                                \
        {                                                                    \
            (A_) = __ldg((const uint4*)(g_q + (size_t)(IA_) * 64) + li);     \
            (P_) = __ldg((const uint4*)(g_q + (size_t)(IP_) * 64) + li);     \
            (N_) = __ldg((const uint4*)(g_q + (size_t)(IN_) * 64) + li);     \
        }

    #define DOTS(A_, P_, N_, DAP_, DAN_)                                     \
        {                                                                    \
            const int* aw = (const int*)&(A_);                               \
            const int* pw = (const int*)&(P_);                               \
            const int* nw = (const int*)&(N_);                               \
            (DAP_) = 0; (DAN_) = 0;                                          \
            _Pragma("unroll")                                                \
            for (int j = 0; j < 4; j++) {                                    \
                (DAP_) = __dp4a(aw[j], pw[j], (DAP_));                       \
                (DAN_) = __dp4a(aw[j], nw[j], (DAN_));                       \
            }                                                                \
            (DAP_) += __shfl_xor_sync(0xFFFFFFFFu, (DAP_), 2);               \
            (DAP_) += __shfl_xor_sync(0xFFFFFFFFu, (DAP_), 1);               \
            (DAN_) += __shfl_xor_sync(0xFFFFFFFFu, (DAN_), 2);               \
            (DAN_) += __shfl_xor_sync(0xFFFFFFFFu, (DAN_), 1);               \
        }

    #define LOSS_ADD(DAP_, DAN_)                                             \
        {                                                                    \
            const float cs_ap = (float)(DAP_) * inv127sq;                    \
            const float cs_an = (float)(DAN_) * inv127sq;                    \
            const float u = fmaf(-10.0f, cs_ap, 5.0f);                       \
            const float v = fmaf( 10.0f, cs_an, -5.0f);                      \
            local += __logf((1.0f + __expf(u)) * (1.0f + __expf(v)));        \
        }

    if (o_beg < o_end) {
        if (all_valid) {
            // -------- unchecked hot path (all octets fully valid) --------
            int o = o_beg;
            unsigned int ia, ip, in;
            LOAD_IDX_U(o, ia, ip, in);
            uint4 A, P, N;
            GATHER(ia, ip, in, A, P, N);

            for (;;) {
                const int on = o + 1;
                const bool have_next = (on < o_end);

                uint4 A2, P2, N2;
                if (have_next) {
                    unsigned int ia2, ip2, in2;
                    LOAD_IDX_U(on, ia2, ip2, in2);
                    GATHER(ia2, ip2, in2, A2, P2, N2);
                }

                int dap, dan;
                DOTS(A, P, N, dap, dan);
                if (li == 0) LOSS_ADD(dap, dan);

                if (!have_next) break;
                A = A2; P = P2; N = N2; o = on;
            }
        } else {
            // -------- checked path (partial final octet) -----------------
            int o = o_beg;
            unsigned int ia, ip, in;
            int t;
            LOAD_IDX_C(o, ia, ip, in, t);
            uint4 A, P, N;
            GATHER(ia, ip, in, A, P, N);

            for (;;) {
                const int on = o + 1;
                const bool have_next = (on < o_end);

                uint4 A2, P2, N2;
                int t2 = 0;
                if (have_next) {
                    unsigned int ia2, ip2, in2;
                    LOAD_IDX_C(on, ia2, ip2, in2, t2);
                    GATHER(ia2, ip2, in2, A2, P2, N2);
                }

                int dap, dan;
                DOTS(A, P, N, dap, dan);
                if (li == 0 && t < n_trip) LOSS_ADD(dap, dan);

                if (!have_next) break;
                A = A2; P = P2; N = N2; t = t2; o = on;
            }
        }
    }
    #undef LOAD_IDX_U
    #undef LOAD_IDX_C
    #undef GATHER
    #undef DOTS
    #undef LOSS_ADD

    // Block reduction
    #pragma unroll
    for (int off = 16; off > 0; off >>= 1)
        local += __shfl_xor_sync(0xFFFFFFFFu, local, off);

    __shared__ float s_part[NTHREADS / 32];
    __shared__ bool  s_last;
    const int warp_in_blk = threadIdx.x >> 5;
    if (lane == 0) s_part[warp_in_blk] = local;
    __syncthreads();
    if (threadIdx.x == 0) {
        float blk = 0.0f;
        #pragma unroll
        for (int i = 0; i < NTHREADS / 32; i++) blk += s_part[i];
        g_part[blockIdx.x] = blk;
        __threadfence();
        const unsigned int prev = atomicAdd(&g_count, 1u);
        s_last = (prev == NBLOCKS - 1);
    }
    __syncthreads();

    // Last finished block: final reduction, output, reset globals for replay.
    if (s_last) {
        double acc = 0.0;
        for (int i = threadIdx.x; i < NBLOCKS; i += NTHREADS)
            acc += (double)g_part[i];
        #pragma unroll
        for (int off = 16; off > 0; off >>= 1)
            acc += __shfl_xor_sync(0xFFFFFFFFu, acc, off);
        __shared__ double s_d[NTHREADS / 32];
        if (lane == 0) s_d[warp_in_blk] = acc;
        __syncthreads();
        if (threadIdx.x == 0) {
            double tot = 0.0;
            #pragma unroll
            for (int i = 0; i < NTHREADS / 32; i++) tot += s_d[i];
            out[0] = (float)(tot / (double)n_trip);
            g_count = 0;
        }
    }
}

extern "C" void kernel_launch(void* const* d_in, const int* in_sizes, int n_in,
                              void* d_out, int out_size)
{
    // Identify inputs by size: feats (32M elems) vs tplts (3M elems).
    int fi = 0, ti = 1;
    if (n_in >= 2 && in_sizes[1] > in_sizes[0]) { fi = 1; ti = 0; }

    const float* feats     = (const float*)d_in[fi];
    const void*  tplts_raw = d_in[ti];
    const int    n_trip    = in_sizes[ti] / 3;
    const int    n_nodes   = in_sizes[fi] / 64;
    float* out = (float*)d_out;

    normalize_kernel<<<NBLOCKS, NTHREADS>>>(feats, n_nodes);
    loss_kernel<<<NBLOCKS, NTHREADS>>>(tplts_raw, n_trip, n_nodes, out);
}

// round 17
// speedup vs baseline: 1.0856x; 1.0428x over previous
#include <cuda_runtime.h>
#include <cuda_fp16.h>
#include <cstdint>

#define NBLOCKS  1184         // 148 SMs * 8 resident blocks -> single wave
#define NTHREADS 256
#define NWARPS   (NBLOCKS * NTHREADS / 32)
#define CAP_NODES 500000

// Device globals (no allocation allowed). Zero-initialized at load.
__device__ unsigned char g_q[(size_t)CAP_NODES * 64];  // 32 MB int8 unit vectors
__device__ float         g_part[NBLOCKS];
__device__ unsigned int  g_count;   // starts 0; last block resets to 0

__device__ __forceinline__ float dot4f(float4 a, float4 b) {
    return a.x * b.x + a.y * b.y + a.z * b.z + a.w * b.w;
}

__device__ __forceinline__ unsigned int pack4_s8(float a, float b, float c, float d) {
    const int ia = __float2int_rn(a), ib = __float2int_rn(b);
    const int ic = __float2int_rn(c), id = __float2int_rn(d);
    return (unsigned int)(ia & 0xFF) | ((unsigned int)(ib & 0xFF) << 8) |
           ((unsigned int)(ic & 0xFF) << 16) | ((unsigned int)(id & 0xFF) << 24);
}

// ---------- Pass 1: normalize rows, store int8 unit vectors (scale 127) ----
__global__ void __launch_bounds__(NTHREADS, 8)
normalize_kernel(const float* __restrict__ feats, int n_nodes)
{
    const int lane = threadIdx.x & 31;
    const int g    = lane >> 3;       // row-group 0..3 within warp
    const int li   = lane & 7;        // lane within group
    const int warp_g = (int)((blockIdx.x * blockDim.x + threadIdx.x) >> 5);

    const int n_quads = (n_nodes + 3) >> 2;

    for (int q = warp_g; q < n_quads; q += NWARPS) {
        const int r = q * 4 + g;
        const bool valid = (r < n_nodes);
        const int rs = valid ? r : 0;

        // Evict-first loads: don't let the fp32 stream evict the int8 table.
        const float4* row = (const float4*)feats + ((long long)rs * 16 + li);
        const float4 v0 = __ldcs(row);
        const float4 v1 = __ldcs(row + 8);

        float nn = dot4f(v0, v0) + dot4f(v1, v1);
        #pragma unroll
        for (int off = 4; off > 0; off >>= 1)
            nn += __shfl_xor_sync(0xFFFFFFFFu, nn, off);

        // norm clamp at 1e-8 (reference eps) == norm^2 clamp at 1e-16
        const float inv = rsqrtf(fmaxf(nn, 1e-16f)) * 127.0f;

        uint2 pack;
        pack.x = pack4_s8(v0.x * inv, v0.y * inv, v0.z * inv, v0.w * inv);
        pack.y = pack4_s8(v1.x * inv, v1.y * inv, v1.z * inv, v1.w * inv);

        if (valid) {
            // 8 lanes x 8B = 64B row, coalesced
            ((uint2*)(g_q + (size_t)rs * 64))[li] = pack;
        }
    }
}

// ---------- Pass 2: triplet loss over int8 unit vectors --------------------
// 4 lanes per vector, 8 triplets per warp-iteration, static contiguous spans,
// simple depth-1 loop with minimal registers -> 8 blocks/SM (64 warps/SM).
__global__ void __launch_bounds__(NTHREADS, 8)
loss_kernel(const void* __restrict__ tplts_raw,
            int n_trip, int n_nodes, float* __restrict__ out)
{
    const int lane = threadIdx.x & 31;
    const int grp  = lane >> 2;       // triplet-group 0..7 within warp
    const int li   = lane & 3;        // lane within group
    const int w    = (int)((blockIdx.x * blockDim.x + threadIdx.x) >> 5);

    // Self-detect index dtype: int64 values < 2^31 -> odd 32-bit words all 0.
    const unsigned int* raw = (const unsigned int*)tplts_raw;
    const unsigned int probe = raw[2 * lane + 1];
    const int is64 = (__ballot_sync(0xFFFFFFFFu, probe != 0u) == 0u) ? 1 : 0;

    // Column base pointers in 32-bit words, with per-element stride.
    const int stride = is64 ? 2 : 1;
    const int* c0 = (const int*)tplts_raw;
    const int* c1 = c0 + n_trip * stride;
    const int* c2 = c1 + n_trip * stride;

    const int n_oct = (n_trip + 7) >> 3;   // 8 triplets per octet
    const unsigned int idx_max =
        (unsigned int)((n_nodes < CAP_NODES ? n_nodes : CAP_NODES) - 1);

    // Static contiguous span for this warp.
    const int per = (n_oct + NWARPS - 1) / NWARPS;
    const int o_beg = w * per;
    const int o_end = min(o_beg + per, n_oct);

    float local = 0.0f;
    const float inv127sq = 1.0f / 16129.0f;   // 1/(127*127)

    for (int o = o_beg; o < o_end; o++) {
        const int t = o * 8 + grp;
        const int ts = min(t, n_trip - 1) * stride;

        const unsigned int ia = min((unsigned int)c0[ts], idx_max);
        const unsigned int ip = min((unsigned int)c1[ts], idx_max);
        const unsigned int in = min((unsigned int)c2[ts], idx_max);

        const uint4 A = __ldg((const uint4*)(g_q + (size_t)ia * 64) + li);
        const uint4 P = __ldg((const uint4*)(g_q + (size_t)ip * 64) + li);
        const uint4 N = __ldg((const uint4*)(g_q + (size_t)in * 64) + li);

        const int* aw = (const int*)&A;
        const int* pw = (const int*)&P;
        const int* nw = (const int*)&N;
        int dap = 0, dan = 0;
        #pragma unroll
        for (int j = 0; j < 4; j++) {
            dap = __dp4a(aw[j], pw[j], dap);
            dan = __dp4a(aw[j], nw[j], dan);
        }
        dap += __shfl_xor_sync(0xFFFFFFFFu, dap, 2);
        dap += __shfl_xor_sync(0xFFFFFFFFu, dap, 1);
        dan += __shfl_xor_sync(0xFFFFFFFFu, dan, 2);
        dan += __shfl_xor_sync(0xFFFFFFFFu, dan, 1);

        if (li == 0) {
            const float cs_ap = (float)dap * inv127sq;
            const float cs_an = (float)dan * inv127sq;
            // u = 5 - 10*cs_ap, v = 10*cs_an - 5 ; both in [-15, 15]:
            // softplus(u)+softplus(v) = log((1+e^u)(1+e^v)), safe in fp32
            const float u = fmaf(-10.0f, cs_ap, 5.0f);
            const float v = fmaf( 10.0f, cs_an, -5.0f);
            const float add = __logf((1.0f + __expf(u)) * (1.0f + __expf(v)));
            local += (t < n_trip) ? add : 0.0f;
        }
    }

    // Block reduction
    #pragma unroll
    for (int off = 16; off > 0; off >>= 1)
        local += __shfl_xor_sync(0xFFFFFFFFu, local, off);

    __shared__ float s_part[NTHREADS / 32];
    __shared__ bool  s_last;
    const int warp_in_blk = threadIdx.x >> 5;
    if (lane == 0) s_part[warp_in_blk] = local;
    __syncthreads();
    if (threadIdx.x == 0) {
        float blk = 0.0f;
        #pragma unroll
        for (int i = 0; i < NTHREADS / 32; i++) blk += s_part[i];
        g_part[blockIdx.x] = blk;
        __threadfence();
        const unsigned int prev = atomicAdd(&g_count, 1u);
        s_last = (prev == NBLOCKS - 1);
    }
    __syncthreads();

    // Last finished block: final reduction, output, reset globals for replay.
    if (s_last) {
        double acc = 0.0;
        for (int i = threadIdx.x; i < NBLOCKS; i += NTHREADS)
            acc += (double)g_part[i];
        #pragma unroll
        for (int off = 16; off > 0; off >>= 1)
            acc += __shfl_xor_sync(0xFFFFFFFFu, acc, off);
        __shared__ double s_d[NTHREADS / 32];
        if (lane == 0) s_d[warp_in_blk] = acc;
        __syncthreads();
        if (threadIdx.x == 0) {
            double tot = 0.0;
            #pragma unroll
            for (int i = 0; i < NTHREADS / 32; i++) tot += s_d[i];
            out[0] = (float)(tot / (double)n_trip);
            g_count = 0;
        }
    }
}

extern "C" void kernel_launch(void* const* d_in, const int* in_sizes, int n_in,
                              void* d_out, int out_size)
{
    // Identify inputs by size: feats (32M elems) vs tplts (3M elems).
    int fi = 0, ti = 1;
    if (n_in >= 2 && in_sizes[1] > in_sizes[0]) { fi = 1; ti = 0; }

    const float* feats     = (const float*)d_in[fi];
    const void*  tplts_raw = d_in[ti];
    const int    n_trip    = in_sizes[ti] / 3;
    const int    n_nodes   = in_sizes[fi] / 64;
    float* out = (float*)d_out;

    normalize_kernel<<<NBLOCKS, NTHREADS>>>(feats, n_nodes);
    loss_kernel<<<NBLOCKS, NTHREADS>>>(tplts_raw, n_trip, n_nodes, out);
}